// round 6
// baseline (speedup 1.0000x reference)
#include <cuda_runtime.h>
#include <math.h>

#define BSZ  2
#define NPT  8192
#define CH   64
#define H_   64
#define W_   160
#define NPIX (H_*W_)        // 10240
#define CSZ  4
#define CX   (W_/CSZ)       // 40
#define CY   (H_/CSZ)       // 16
#define NC   (CX*CY)        // 640

// Static scratch
__device__ float4 g_ptp[BSZ*NPT];        // (ux, uy, Su, idx-bits) original order
__device__ float4 g_bin[BSZ*NPT];        // points sorted by cell
__device__ int    g_start[BSZ*(NC+1)];
__device__ float  g_f3dT[BSZ*NPT*CH];    // feat_3d transposed [b][n][c]

// ---------------- helpers ----------------
__device__ __forceinline__ float d2of(float4 p, float gxf, float gyf, float sg) {
    float m   = __fmul_rn(gxf, p.x);            // rn(gx*ux)
    float dot = __fmaf_rn(gyf, p.y, m);         // fma(gy,uy, m)
    float t1  = __fadd_rn(sg, p.z);             // rn(Sg + Su)
    return __fmaf_rn(-2.f, dot, t1);            // rn(t1 - 2*dot)
}

__device__ __forceinline__ void ins3(float d2, int idx,
    float& bd0, float& bd1, float& bd2, int& bi0, int& bi1, int& bi2) {
    if (d2 < bd2 || (d2 == bd2 && idx < bi2)) {
        bool l1 = (d2 < bd1) || (d2 == bd1 && idx < bi1);
        bool l0 = (d2 < bd0) || (d2 == bd0 && idx < bi0);
        if (l0)      { bd2=bd1; bi2=bi1; bd1=bd0; bi1=bi0; bd0=d2; bi0=idx; }
        else if (l1) { bd2=bd1; bi2=bi1; bd1=d2;  bi1=idx; }
        else         { bd2=d2;  bi2=idx; }
    }
}

// ---------------- K1: binning (blocks 0..1) + transpose (R3-verbatim) ----------------
__global__ void __launch_bounds__(1024) k_prep(const float* __restrict__ uv,
                                               const float* __restrict__ f3d) {
    __shared__ int s_cnt[NC];
    __shared__ int s_scan[1024];
    __shared__ int s_curc[NC];
    __shared__ float tile[32][33];

    int t = threadIdx.x;
    if (blockIdx.x < BSZ) {
        int b = blockIdx.x;
        for (int i = t; i < NC; i += 1024) s_cnt[i] = 0;
        __syncthreads();
        float ux[8], uy[8], su[8]; int cl[8];
        #pragma unroll
        for (int k = 0; k < 8; k++) {
            int n = t + k*1024;
            ux[k] = uv[(b*2+0)*NPT + n];
            uy[k] = uv[(b*2+1)*NPT + n];
            // match jnp.sum(uv*uv): rn squares + rn add (no fma)
            su[k] = __fadd_rn(__fmul_rn(ux[k],ux[k]), __fmul_rn(uy[k],uy[k]));
            int cx = min((int)(ux[k]*0.25f), CX-1);
            int cy = min((int)(uy[k]*0.25f), CY-1);
            cl[k] = cy*CX + cx;
            g_ptp[b*NPT + n] = make_float4(ux[k], uy[k], su[k], __int_as_float(n));
            atomicAdd(&s_cnt[cl[k]], 1);
        }
        __syncthreads();
        int v = (t < NC) ? s_cnt[t] : 0;
        s_scan[t] = v;
        __syncthreads();
        #pragma unroll
        for (int off = 1; off < 1024; off <<= 1) {
            int tmp = (t >= off) ? s_scan[t-off] : 0;
            __syncthreads();
            s_scan[t] += tmp;
            __syncthreads();
        }
        if (t < NC) { int st0 = s_scan[t] - v; g_start[b*(NC+1)+t] = st0; s_curc[t] = st0; }
        if (t == 0) g_start[b*(NC+1)+NC] = NPT;
        __syncthreads();
        #pragma unroll
        for (int k = 0; k < 8; k++) {
            int n = t + k*1024;
            int pos = atomicAdd(&s_curc[cl[k]], 1);
            g_bin[b*NPT + pos] = make_float4(ux[k], uy[k], su[k], __int_as_float(n));
        }
    } else {
        // transpose feat_3d [b][c][n] -> [b][n][c]
        int bid = blockIdx.x - BSZ;           // 0..1023
        int nt = bid & 255;
        int ct = (bid >> 8) & 1;
        int b  = bid >> 9;
        int tx = t & 31, ty = t >> 5;
        int n0 = nt*32, c0 = ct*32;
        tile[ty][tx] = f3d[((long)b*CH + c0+ty)*NPT + n0+tx];
        __syncthreads();
        g_f3dT[((long)b*NPT + n0+ty)*CH + c0+tx] = tile[tx][ty];
    }
}

// ---------------- K2: fused query + MLP, one block per cell (16 pixels) ----------------
__global__ void __launch_bounds__(512, 3) k_main(
    const float* __restrict__ w1, const float* __restrict__ b1,
    const float* __restrict__ w2, const float* __restrict__ b2,
    const float* __restrict__ w3, const float* __restrict__ b3,
    float* __restrict__ out)
{
    __shared__ float s_w1[48], s_b1[16], s_w2[64*17], s_b2[64], s_b3[64];
    __shared__ float s_w3[64*68];
    __shared__ int s_rlo[3], s_rhi[3];
    __shared__ float s_td[16][48];          // 16 lanes x 3 partial triples
    __shared__ int   s_ti[16][48];
    __shared__ float4 s_si[16][3];          // (ox,oy,norm,idx-bits)
    __shared__ float s_h1[3][16][16];       // [k][px][o]
    __shared__ float s_fin[16][68];         // [px][c] padded
    __shared__ float s_out[64][17];         // [o][px]

    int t = threadIdx.x;
    int b = blockIdx.x / NC, cell = blockIdx.x % NC;
    int cx = cell % CX, cy = cell / CX;

    // weight prefetch (LDGs overlap the query)
    for (int i = t; i < 48;   i += 512) s_w1[i] = w1[i];
    for (int i = t; i < 16;   i += 512) s_b1[i] = b1[i];
    for (int i = t; i < 1024; i += 512) s_w2[(i>>4)*17 + (i&15)] = w2[i];
    for (int i = t; i < 64;   i += 512) { s_b2[i] = b2[i]; s_b3[i] = b3[i]; }
    for (int i = t; i < 1024; i += 512) {
        float4 v = ((const float4*)w3)[i];
        *(float4*)&s_w3[(i>>4)*68 + ((i&15)<<2)] = v;
    }

    const int*    st  = &g_start[b*(NC+1)];
    const float4* bin = &g_bin[b*NPT];

    if (t == 0) {
        int y0 = max(cy-1,0), y1 = min(cy+1,CY-1);
        int xlo = max(cx-1,0), xhi = min(cx+1,CX-1);
        int n = 0;
        for (int yy = y0; yy <= y1; yy++) {
            s_rlo[n] = st[yy*CX + xlo];
            s_rhi[n] = st[yy*CX + xhi + 1];
            n++;
        }
        for (; n < 3; n++) { s_rlo[n] = 0; s_rhi[n] = 0; }
    }
    __syncthreads();

    // ---- scan: 16 threads per pixel over 3x3-cell ranges, direct from gmem ----
    if (t < 256) {
        int px = t >> 4, j = t & 15;
        int gx = (cx<<2) + (px&3), gy = (cy<<2) + (px>>2);
        float gxf = (float)gx, gyf = (float)gy;
        float sg = (float)(gx*gx + gy*gy);
        float bd0=3.4e38f, bd1=3.4e38f, bd2=3.4e38f;
        int   bi0=0x7fffffff, bi1=0x7fffffff, bi2=0x7fffffff;
        #pragma unroll
        for (int r = 0; r < 3; r++) {
            int lo = s_rlo[r], hi = s_rhi[r];
            for (int i = lo + j; i < hi; i += 16) {
                float4 p = bin[i];
                ins3(d2of(p,gxf,gyf,sg), __float_as_int(p.w), bd0,bd1,bd2,bi0,bi1,bi2);
            }
        }
        s_td[px][j*3+0]=bd0; s_ti[px][j*3+0]=bi0;
        s_td[px][j*3+1]=bd1; s_ti[px][j*3+1]=bi1;
        s_td[px][j*3+2]=bd2; s_ti[px][j*3+2]=bi2;
    }
    __syncthreads();

    // ---- per-pixel leader: merge 48 partials; rare ring>=2 fallback (R3-proven) ----
    if (t < 16) {
        int px = t;
        int gx = (cx<<2) + (px&3), gy = (cy<<2) + (px>>2);
        float gxf = (float)gx, gyf = (float)gy;
        float sg = (float)(gx*gx + gy*gy);
        float bd0=3.4e38f, bd1=3.4e38f, bd2=3.4e38f;
        int   bi0=0x7fffffff, bi1=0x7fffffff, bi2=0x7fffffff;
        #pragma unroll
        for (int j = 0; j < 48; j++)
            ins3(s_td[px][j], s_ti[px][j], bd0,bd1,bd2,bi0,bi1,bi2);
        // rings 0..1 fully covered; unscanned exact dist >= 4 -> d2 >= 16-eps
        bool done = (bd2 < 15.f);
        for (int r = 2; !done && r < 64; r++) {
            int x0 = max(cx-r,0), x1 = min(cx+r,CX-1);
            int yy0 = max(cy-r,0), yy1 = min(cy+r,CY-1);
            for (int yy = yy0; yy <= yy1; yy++) {
                if (yy == cy-r || yy == cy+r) {
                    int lo = st[yy*CX + x0], hi = st[yy*CX + x1 + 1];
                    for (int i = lo; i < hi; i++) {
                        float4 p = bin[i];
                        ins3(d2of(p,gxf,gyf,sg), __float_as_int(p.w), bd0,bd1,bd2,bi0,bi1,bi2);
                    }
                } else {
                    if (cx-r >= 0) {
                        int ci = yy*CX + (cx-r);
                        for (int i = st[ci]; i < st[ci+1]; i++) {
                            float4 p = bin[i];
                            ins3(d2of(p,gxf,gyf,sg), __float_as_int(p.w), bd0,bd1,bd2,bi0,bi1,bi2);
                        }
                    }
                    if (cx+r <= CX-1) {
                        int ci = yy*CX + (cx+r);
                        for (int i = st[ci]; i < st[ci+1]; i++) {
                            float4 p = bin[i];
                            ins3(d2of(p,gxf,gyf,sg), __float_as_int(p.w), bd0,bd1,bd2,bi0,bi1,bi2);
                        }
                    }
                }
            }
            if (bd2 < (float)(16*r*r) - 1.f) done = true;
            if (x0==0 && yy0==0 && x1==CX-1 && yy1==CY-1) done = true;
        }
        int ids[3] = {bi0, bi1, bi2};
        #pragma unroll
        for (int k = 0; k < 3; k++) {
            float4 p = g_ptp[b*NPT + ids[k]];
            float ox = p.x - gxf;
            float oy = p.y - gyf;
            float nm = sqrtf(__fadd_rn(__fmul_rn(ox,ox), __fmul_rn(oy,oy)));
            s_si[px][k] = make_float4(ox, oy, nm, p.w);
        }
    }
    __syncthreads();

    // ---- Phase A: h1 = relu(w1 @ [ox,oy,norm] + b1), k-planes ----
    {
        int lane = t & 63;
        if (lane < 48) {
            #pragma unroll
            for (int it = 0; it < 2; it++) {
                int px = (t>>6) + (it<<3);
                int o = lane / 3, k = lane % 3;
                float4 si = s_si[px][k];
                float acc = s_b1[o];
                acc = fmaf(s_w1[o*3+0], si.x, acc);
                acc = fmaf(s_w1[o*3+1], si.y, acc);
                acc = fmaf(s_w1[o*3+2], si.z, acc);
                s_h1[k][px][o] = fmaxf(acc, 0.f);
            }
        }
    }
    __syncthreads();

    // ---- Phase B (per-channel score!): fin[c] = sum_k sigmoid(w2@h1)_c,k * f3d[c,idx_k] ----
    {
        int c = t & 63;
        #pragma unroll
        for (int it = 0; it < 2; it++) {
            int px = (t>>6) + (it<<3);
            float a0 = s_b2[c], a1 = a0, a2 = a0;
            #pragma unroll
            for (int j = 0; j < 16; j++) {
                float wv = s_w2[c*17+j];
                a0 = fmaf(wv, s_h1[0][px][j], a0);
                a1 = fmaf(wv, s_h1[1][px][j], a1);
                a2 = fmaf(wv, s_h1[2][px][j], a2);
            }
            float sc0 = __fdividef(1.f, 1.f + __expf(-a0));
            float sc1 = __fdividef(1.f, 1.f + __expf(-a1));
            float sc2 = __fdividef(1.f, 1.f + __expf(-a2));
            int i0 = __float_as_int(s_si[px][0].w);
            int i1 = __float_as_int(s_si[px][1].w);
            int i2 = __float_as_int(s_si[px][2].w);
            float f0 = g_f3dT[((long)(b*NPT) + i0)*CH + c];
            float f1 = g_f3dT[((long)(b*NPT) + i1)*CH + c];
            float f2 = g_f3dT[((long)(b*NPT) + i2)*CH + c];
            s_fin[px][c] = sc0*f0 + sc1*f1 + sc2*f2;
        }
    }
    __syncthreads();

    // ---- Phase C: out = relu(w3 @ fin + b3) (R3-proven) ----
    {
        int o = t >> 3;
        #pragma unroll
        for (int it = 0; it < 2; it++) {
            int p2 = (t&7) + (it<<3);
            float acc = s_b3[o];
            #pragma unroll
            for (int c = 0; c < 64; c += 4) {
                float4 wv = *(const float4*)&s_w3[o*68 + c];
                float4 fv = *(const float4*)&s_fin[p2][c];
                acc = fmaf(wv.x, fv.x, acc);
                acc = fmaf(wv.y, fv.y, acc);
                acc = fmaf(wv.z, fv.z, acc);
                acc = fmaf(wv.w, fv.w, acc);
            }
            s_out[o][p2] = fmaxf(acc, 0.f);
        }
    }
    __syncthreads();

    // ---- store: STG.128 rows of 4 px ----
    if (t < 256) {
        int o = t >> 2, ry = t & 3;
        float4 v = make_float4(s_out[o][ry*4+0], s_out[o][ry*4+1],
                               s_out[o][ry*4+2], s_out[o][ry*4+3]);
        *(float4*)&out[((long)(b*CH) + o)*NPIX + (cy*4+ry)*W_ + cx*4] = v;
    }
}

extern "C" void kernel_launch(void* const* d_in, const int* in_sizes, int n_in,
                              void* d_out, int out_size) {
    const float* uv  = (const float*)d_in[0];
    // d_in[1] = feat_2d : unused by the reference computation
    const float* f3d = (const float*)d_in[2];
    const float* w1  = (const float*)d_in[3];
    const float* b1  = (const float*)d_in[4];
    const float* w2  = (const float*)d_in[5];
    const float* b2  = (const float*)d_in[6];
    const float* w3  = (const float*)d_in[7];
    const float* b3  = (const float*)d_in[8];
    float* out = (float*)d_out;

    k_prep<<<BSZ + 1024, 1024>>>(uv, f3d);
    k_main<<<BSZ*NC, 512>>>(w1, b1, w2, b2, w3, b3, out);
}